// round 15
// baseline (speedup 1.0000x reference)
#include <cuda_runtime.h>
#include <cuda_fp16.h>
#include <stdint.h>
#include <math.h>

#define BATCH 4096
#define HID   1024
#define STEPS 16
#define BK    64
#define NCH   (HID / BK)   // 16 k-chunks

// stage: Ahi/Alo/Bh, each 128 rows x 128B (swizzled) = 48KB
#define ST_AHI 0
#define ST_ALO 16384
#define ST_BH  32768
#define ST_SZ  49152
#define NSTAGE 3
#define SMEM_TOTAL (NSTAGE * ST_SZ)   // 147456

// ---------------- device scratch (no allocations) ----------------
// Folded gate weights, single fp16. Rows: (g*HID + j) x K, g in {r,z,in,hn}
//   sel 0: steps >= 1 (x==h): r/z = W_ih+W_hh, in = W_ih_n, hn = W_hh_n
//   sel 1: step 0    (x==0):  r/z = W_hh,      in = 0,      hn = W_hh_n
__device__ __align__(16) __half g_Wf[2][4 * HID * HID];
__device__ __align__(16) __half g_WOf[HID * HID];
__device__ __align__(16) __half g_hhi[2][BATCH * HID];   // h split hi (fp16)
__device__ __align__(16) __half g_hlo[2][BATCH * HID];   // h split lo (fp16)
__device__ __align__(16) __half g_rhi[BATCH * HID];      // relu(h) split hi
__device__ __align__(16) __half g_rlo[BATCH * HID];      // relu(h) split lo
__device__ __align__(16) float g_b4[4 * HID];

// ---------------- helpers ----------------
__device__ __forceinline__ uint32_t smem_u32(const void* p) {
    uint32_t a;
    asm("{ .reg .u64 t; cvta.to.shared.u64 t, %1; cvt.u32.u64 %0, t; }" : "=r"(a) : "l"(p));
    return a;
}
__device__ __forceinline__ void cp16(uint32_t s, const void* g) {
    asm volatile("cp.async.cg.shared.global [%0], [%1], 16;" :: "r"(s), "l"(g));
}
#define CP_COMMIT() asm volatile("cp.async.commit_group;" ::: "memory")
#define CP_WAIT1()  asm volatile("cp.async.wait_group 1;" ::: "memory")

#define LDSM4(d, addr) \
    asm volatile("ldmatrix.sync.aligned.m8n8.x4.shared.b16 {%0,%1,%2,%3}, [%4];" \
        : "=r"((d)[0]), "=r"((d)[1]), "=r"((d)[2]), "=r"((d)[3]) : "r"(addr))
#define LDSM2(d0, d1, addr) \
    asm volatile("ldmatrix.sync.aligned.m8n8.x2.shared.b16 {%0,%1}, [%2];" \
        : "=r"(d0), "=r"(d1) : "r"(addr))
#define MMA(c, a, b0, b1) \
    asm volatile("mma.sync.aligned.m16n8k16.row.col.f32.f16.f16.f32 " \
        "{%0,%1,%2,%3}, {%4,%5,%6,%7}, {%8,%9}, {%0,%1,%2,%3};" \
        : "+f"((c)[0]), "+f"((c)[1]), "+f"((c)[2]), "+f"((c)[3]) \
        : "r"((a)[0]), "r"((a)[1]), "r"((a)[2]), "r"((a)[3]), "r"(b0), "r"(b1))

__device__ __forceinline__ float sigf(float x) { return 1.0f / (1.0f + __expf(-x)); }
__device__ __forceinline__ float tanh_fast(float x) {
    float e = __expf(2.0f * x);
    return 1.0f - 2.0f / (e + 1.0f);
}
__device__ __forceinline__ void split_f16(float v, __half& hi, __half& lo) {
    hi = __float2half_rn(v);
    lo = __float2half_rn(v - __half2float(hi));
}
__device__ __forceinline__ uint32_t pack2h(__half a, __half b) {
    __half2 t; t.x = a; t.y = b; return *(uint32_t*)&t;
}

// loader (256 threads): row lr=tid>>1, half cp0=(tid&1)*4; 3 subtiles x 4 cp16
#define LOAD_STAGE(stoff, k0) do {                                                 \
    _Pragma("unroll")                                                              \
    for (int i = 0; i < 4; ++i) {                                                  \
        int c = cp0 + i;                                                           \
        uint32_t so = (uint32_t)(lr * 128 + ((c ^ (lr & 7)) << 4));                \
        cp16(sb + (stoff) + ST_AHI + so, pAhi + (k0) + c * 8);                     \
        cp16(sb + (stoff) + ST_ALO + so, pAlo + (k0) + c * 8);                     \
        cp16(sb + (stoff) + ST_BH  + so, pB   + (k0) + c * 8);                     \
    }                                                                              \
    CP_COMMIT();                                                                   \
} while (0)

// ---------------- prep kernels ----------------
__global__ void prep_fold(const float* __restrict__ W_ih, const float* __restrict__ W_hh,
                          const float* __restrict__ b_ih, const float* __restrict__ b_hh) {
    int idx = blockIdx.x * 256 + threadIdx.x;
    if (idx >= 4 * HID * HID) return;
    int k = idx & (HID - 1);
    int j = (idx >> 10) & (HID - 1);
    int g = idx >> 20;

    float w, ws1;
    if (g == 0) {
        float a = W_ih[j * HID + k], b = W_hh[j * HID + k];
        w = a + b; ws1 = b;
    } else if (g == 1) {
        int r = HID + j;
        float a = W_ih[r * HID + k], b = W_hh[r * HID + k];
        w = a + b; ws1 = b;
    } else if (g == 2) {
        int r = 2 * HID + j;
        w = W_ih[r * HID + k]; ws1 = 0.0f;
    } else {
        int r = 2 * HID + j;
        w = W_hh[r * HID + k]; ws1 = w;
    }
    g_Wf[0][idx] = __float2half_rn(w);
    g_Wf[1][idx] = __float2half_rn(ws1);

    if (k == 0) {
        float bb;
        if (g == 0)      bb = b_ih[j] + b_hh[j];
        else if (g == 1) bb = b_ih[HID + j] + b_hh[HID + j];
        else if (g == 2) bb = b_ih[2 * HID + j];
        else             bb = b_hh[2 * HID + j];
        g_b4[g * HID + j] = bb;
    }
}

__global__ void prep_wout(const float* __restrict__ W_out) {
    int idx = blockIdx.x * 256 + threadIdx.x;
    if (idx >= HID * HID) return;
    g_WOf[idx] = __float2half_rn(W_out[idx]);
}

__global__ void prep_h(const float* __restrict__ hidden) {
    int idx = blockIdx.x * 256 + threadIdx.x;
    if (idx >= BATCH * HID) return;
    __half hi, lo;
    split_f16(hidden[idx], hi, lo);
    g_hhi[0][idx] = hi; g_hlo[0][idx] = lo;
}

// ---------------- gate GEMM + GRU pointwise ----------------
// grid (32, 32): bx = 32-j tile, by = 128-row batch tile. CTA N = 4 gates x 32 j.
// 8 warps, 2x4 grid, warp tile 64x32. 2 split passes: (Ah + Al) x Bh.
__global__ __launch_bounds__(256, 1)
void gate_mma(int wsel, int src, int dst) {
    extern __shared__ char smem[];
    uint32_t sb = smem_u32(smem);
    int tid = threadIdx.x;
    int lane = tid & 31, wid = tid >> 5;
    int wm = wid >> 2, wn = wid & 3;
    int rowbase = blockIdx.y * 128;
    int jbase   = blockIdx.x * 32;

    // loader mapping
    int lr = tid >> 1;
    int cp0 = (tid & 1) * 4;
    const __half* pAhi = g_hhi[src] + (size_t)(rowbase + lr) * HID;
    const __half* pAlo = g_hlo[src] + (size_t)(rowbase + lr) * HID;
    const __half* pB = g_Wf[wsel] + (size_t)((lr >> 5) * HID + jbase + (lr & 31)) * HID;

    float acc[4][4][4];
#pragma unroll
    for (int a = 0; a < 4; ++a)
#pragma unroll
        for (int b = 0; b < 4; ++b)
#pragma unroll
            for (int c = 0; c < 4; ++c) acc[a][b][c] = 0.0f;

    LOAD_STAGE(0, 0);
    LOAD_STAGE(ST_SZ, BK);

    int a_row0 = wm * 64 + (lane & 15);
    int a_chi = lane >> 4;
    int b_row0 = wn * 32 + (lane & 7);
    int b_chi = (lane >> 3) & 1;

    for (int cc = 0; cc < NCH; ++cc) {
        uint32_t st = sb + (uint32_t)((cc % 3) * ST_SZ);
        CP_WAIT1();
        __syncthreads();
        if (cc + 2 < NCH) {
            uint32_t st2 = (uint32_t)(((cc + 2) % 3) * ST_SZ);
            int k0 = (cc + 2) * BK;
            LOAD_STAGE(st2, k0);
        } else {
            CP_COMMIT();
        }

#pragma unroll
        for (int kk = 0; kk < 4; ++kk) {
            uint32_t Ah[4][4], Al[4][4];
#pragma unroll
            for (int mf = 0; mf < 4; ++mf) {
                int row = a_row0 + mf * 16;
                uint32_t so = (uint32_t)(row * 128 + (((2 * kk + a_chi) ^ (row & 7)) << 4));
                LDSM4(Ah[mf], st + ST_AHI + so);
                LDSM4(Al[mf], st + ST_ALO + so);
            }
            uint32_t bh[4][2];
#pragma unroll
            for (int nf = 0; nf < 4; ++nf) {
                int row = b_row0 + nf * 8;
                uint32_t so = (uint32_t)(row * 128 + (((2 * kk + b_chi) ^ (row & 7)) << 4));
                LDSM2(bh[nf][0], bh[nf][1], st + ST_BH + so);
            }
            // pass 1: Ah x Bh ; pass 2: Al x Bh
#pragma unroll
            for (int nf = 0; nf < 4; ++nf)
#pragma unroll
                for (int mf = 0; mf < 4; ++mf)
                    MMA(acc[mf][nf], Ah[mf], bh[nf][0], bh[nf][1]);
#pragma unroll
            for (int nf = 0; nf < 4; ++nf)
#pragma unroll
                for (int mf = 0; mf < 4; ++mf)
                    MMA(acc[mf][nf], Al[mf], bh[nf][0], bh[nf][1]);
        }
    }
    __syncthreads();

    // ---- exchange accs through smem: Cs[128][132] ----
    float* Cs = (float*)smem;
#pragma unroll
    for (int mf = 0; mf < 4; ++mf)
#pragma unroll
        for (int nf = 0; nf < 4; ++nf) {
            int m = wm * 64 + mf * 16 + (lane >> 2);
            int n = wn * 32 + nf * 8 + (lane & 3) * 2;
            Cs[m * 132 + n]           = acc[mf][nf][0];
            Cs[m * 132 + n + 1]       = acc[mf][nf][1];
            Cs[(m + 8) * 132 + n]     = acc[mf][nf][2];
            Cs[(m + 8) * 132 + n + 1] = acc[mf][nf][3];
        }
    __syncthreads();

    // ---- GRU pointwise: thread -> row m=tid/2, 16 j values ----
    {
        int m = tid >> 1;
        int j0l = (tid & 1) * 16;
        int j0 = jbase + j0l;
        size_t hoff = (size_t)(rowbase + m) * HID + j0;

        __half hhb[16], hlb[16];
        *(uint4*)&hhb[0] = *(const uint4*)(g_hhi[src] + hoff);
        *(uint4*)&hhb[8] = *(const uint4*)(g_hhi[src] + hoff + 8);
        *(uint4*)&hlb[0] = *(const uint4*)(g_hlo[src] + hoff);
        *(uint4*)&hlb[8] = *(const uint4*)(g_hlo[src] + hoff + 8);

        uint32_t ohh[8], ohl[8], orh[8], orl[8];
#pragma unroll
        for (int p = 0; p < 8; ++p) {
            __half ehh[2], ehl[2], erh[2], erl[2];
#pragma unroll
            for (int u = 0; u < 2; ++u) {
                int i = 2 * p + u;
                int jl = j0l + i;
                int j = j0 + i;
                float vr = Cs[m * 132 + jl]      + g_b4[j];
                float vz = Cs[m * 132 + 32 + jl] + g_b4[HID + j];
                float vi = Cs[m * 132 + 64 + jl] + g_b4[2 * HID + j];
                float vh = Cs[m * 132 + 96 + jl] + g_b4[3 * HID + j];
                float rg = sigf(vr);
                float zz = sigf(vz);
                float nn = tanh_fast(vi + rg * vh);
                float hp = __half2float(hhb[i]) + __half2float(hlb[i]);
                float hn = (1.0f - zz) * nn + zz * hp;
                split_f16(hn, ehh[u], ehl[u]);
                split_f16(fmaxf(hn, 0.0f), erh[u], erl[u]);
            }
            ohh[p] = pack2h(ehh[0], ehh[1]);
            ohl[p] = pack2h(ehl[0], ehl[1]);
            orh[p] = pack2h(erh[0], erh[1]);
            orl[p] = pack2h(erl[0], erl[1]);
        }
        *(uint4*)(g_hhi[dst] + hoff)     = make_uint4(ohh[0], ohh[1], ohh[2], ohh[3]);
        *(uint4*)(g_hhi[dst] + hoff + 8) = make_uint4(ohh[4], ohh[5], ohh[6], ohh[7]);
        *(uint4*)(g_hlo[dst] + hoff)     = make_uint4(ohl[0], ohl[1], ohl[2], ohl[3]);
        *(uint4*)(g_hlo[dst] + hoff + 8) = make_uint4(ohl[4], ohl[5], ohl[6], ohl[7]);
        *(uint4*)(g_rhi + hoff)          = make_uint4(orh[0], orh[1], orh[2], orh[3]);
        *(uint4*)(g_rhi + hoff + 8)      = make_uint4(orh[4], orh[5], orh[6], orh[7]);
        *(uint4*)(g_rlo + hoff)          = make_uint4(orl[0], orl[1], orl[2], orl[3]);
        *(uint4*)(g_rlo + hoff + 8)      = make_uint4(orl[4], orl[5], orl[6], orl[7]);
    }
}

// ---------------- output projection ----------------
// grid (8, 32): bx = 128-col tile, by = 128-row batch tile. 8 warps, 2x4, 64x32.
__global__ __launch_bounds__(256, 1)
void out_mma(const float* __restrict__ bout, float* __restrict__ out) {
    extern __shared__ char smem[];
    uint32_t sb = smem_u32(smem);
    int tid = threadIdx.x;
    int lane = tid & 31, wid = tid >> 5;
    int wm = wid >> 2, wn = wid & 3;
    int rowbase = blockIdx.y * 128;
    int colbase = blockIdx.x * 128;

    int lr = tid >> 1;
    int cp0 = (tid & 1) * 4;
    const __half* pAhi = g_rhi + (size_t)(rowbase + lr) * HID;
    const __half* pAlo = g_rlo + (size_t)(rowbase + lr) * HID;
    const __half* pB = g_WOf + (size_t)(colbase + lr) * HID;

    float acc[4][4][4];
#pragma unroll
    for (int a = 0; a < 4; ++a)
#pragma unroll
        for (int b = 0; b < 4; ++b)
#pragma unroll
            for (int c = 0; c < 4; ++c) acc[a][b][c] = 0.0f;

    LOAD_STAGE(0, 0);
    LOAD_STAGE(ST_SZ, BK);

    int a_row0 = wm * 64 + (lane & 15);
    int a_chi = lane >> 4;
    int b_row0 = wn * 32 + (lane & 7);
    int b_chi = (lane >> 3) & 1;

    for (int cc = 0; cc < NCH; ++cc) {
        uint32_t st = sb + (uint32_t)((cc % 3) * ST_SZ);
        CP_WAIT1();
        __syncthreads();
        if (cc + 2 < NCH) {
            uint32_t st2 = (uint32_t)(((cc + 2) % 3) * ST_SZ);
            int k0 = (cc + 2) * BK;
            LOAD_STAGE(st2, k0);
        } else {
            CP_COMMIT();
        }

#pragma unroll
        for (int kk = 0; kk < 4; ++kk) {
            uint32_t Ah[4][4], Al[4][4];
#pragma unroll
            for (int mf = 0; mf < 4; ++mf) {
                int row = a_row0 + mf * 16;
                uint32_t so = (uint32_t)(row * 128 + (((2 * kk + a_chi) ^ (row & 7)) << 4));
                LDSM4(Ah[mf], st + ST_AHI + so);
                LDSM4(Al[mf], st + ST_ALO + so);
            }
            uint32_t bh[4][2];
#pragma unroll
            for (int nf = 0; nf < 4; ++nf) {
                int row = b_row0 + nf * 8;
                uint32_t so = (uint32_t)(row * 128 + (((2 * kk + b_chi) ^ (row & 7)) << 4));
                LDSM2(bh[nf][0], bh[nf][1], st + ST_BH + so);
            }
#pragma unroll
            for (int nf = 0; nf < 4; ++nf)
#pragma unroll
                for (int mf = 0; mf < 4; ++mf)
                    MMA(acc[mf][nf], Ah[mf], bh[nf][0], bh[nf][1]);
#pragma unroll
            for (int nf = 0; nf < 4; ++nf)
#pragma unroll
                for (int mf = 0; mf < 4; ++mf)
                    MMA(acc[mf][nf], Al[mf], bh[nf][0], bh[nf][1]);
        }
    }

    // ---- bias epilogue, direct from fragments ----
#pragma unroll
    for (int mf = 0; mf < 4; ++mf)
#pragma unroll
        for (int nf = 0; nf < 4; ++nf) {
            int m = rowbase + wm * 64 + mf * 16 + (lane >> 2);
            int n = colbase + wn * 32 + nf * 8 + (lane & 3) * 2;
            float b0 = bout[n], b1 = bout[n + 1];
            float2 v0 = make_float2(acc[mf][nf][0] + b0, acc[mf][nf][1] + b1);
            float2 v1 = make_float2(acc[mf][nf][2] + b0, acc[mf][nf][3] + b1);
            *(float2*)(out + (size_t)m * 1024 + n)       = v0;
            *(float2*)(out + (size_t)(m + 8) * 1024 + n) = v1;
        }
}

// ---------------- launch ----------------
extern "C" void kernel_launch(void* const* d_in, const int* in_sizes, int n_in,
                              void* d_out, int out_size) {
    const float* hidden = (const float*)d_in[0];  // (1, 4096, 1024)
    const float* W_ih   = (const float*)d_in[1];  // (3072, 1024)
    const float* W_hh   = (const float*)d_in[2];  // (3072, 1024)
    const float* b_ih   = (const float*)d_in[3];
    const float* b_hh   = (const float*)d_in[4];
    const float* W_out  = (const float*)d_in[5];  // (1024, 1024)
    const float* b_out  = (const float*)d_in[6];
    float* out = (float*)d_out;                    // (16, 4096, 1024)

    cudaFuncSetAttribute(gate_mma, cudaFuncAttributeMaxDynamicSharedMemorySize, SMEM_TOTAL);
    cudaFuncSetAttribute(out_mma,  cudaFuncAttributeMaxDynamicSharedMemorySize, SMEM_TOTAL);

    prep_fold<<<(4 * HID * HID) / 256, 256>>>(W_ih, W_hh, b_ih, b_hh);
    prep_wout<<<(HID * HID) / 256, 256>>>(W_out);
    prep_h<<<(BATCH * HID) / 256, 256>>>(hidden);

    dim3 ggrid(32, 32);
    dim3 ogrid(8, 32);

    for (int t = 0; t < STEPS; ++t) {
        int wsel = (t == 0) ? 1 : 0;
        int src = t & 1;
        int dst = (t + 1) & 1;
        gate_mma<<<ggrid, 256, SMEM_TOTAL>>>(wsel, src, dst);
        out_mma<<<ogrid, 256, SMEM_TOTAL>>>(b_out, out + (size_t)t * BATCH * 1024);
    }
}

// round 17
// speedup vs baseline: 1.9026x; 1.9026x over previous
#include <cuda_runtime.h>
#include <cuda_fp16.h>
#include <stdint.h>
#include <math.h>

#define BATCH 4096
#define HID   1024
#define STEPS 16
#define BK    64
#define NCH   (HID / BK)   // 16 k-chunks

// stage: A 128x128B + B 128x128B = 32KB
#define ST_A   0
#define ST_B   16384
#define ST_SZ  32768
#define NSTAGE 3
#define SMEM_TOTAL (NSTAGE * ST_SZ)   // 98304 (x2 CTAs/SM = 192KB)

// ---------------- device scratch (no allocations) ----------------
// Folded gate weights, single fp16. Rows: (g*HID + j) x K, g in {r,z,in,hn}
//   sel 0: steps >= 1 (x==h): r/z = W_ih+W_hh, in = W_ih_n, hn = W_hh_n
//   sel 1: step 0    (x==0):  r/z = W_hh,      in = 0,      hn = W_hh_n
__device__ __align__(16) __half g_Wf[2][4 * HID * HID];
__device__ __align__(16) __half g_WOf[HID * HID];
__device__ __align__(16) __half g_hhi[2][BATCH * HID];   // h hi (GEMM operand)
__device__ __align__(16) __half g_hlo[2][BATCH * HID];   // h lo (carry accuracy only)
__device__ __align__(16) __half g_rhi[BATCH * HID];      // relu(h) hi (out GEMM operand)
__device__ __align__(16) float g_b4[4 * HID];

// ---------------- helpers ----------------
__device__ __forceinline__ uint32_t smem_u32(const void* p) {
    uint32_t a;
    asm("{ .reg .u64 t; cvta.to.shared.u64 t, %1; cvt.u32.u64 %0, t; }" : "=r"(a) : "l"(p));
    return a;
}
__device__ __forceinline__ void cp16(uint32_t s, const void* g) {
    asm volatile("cp.async.cg.shared.global [%0], [%1], 16;" :: "r"(s), "l"(g));
}
#define CP_COMMIT() asm volatile("cp.async.commit_group;" ::: "memory")
#define CP_WAIT1()  asm volatile("cp.async.wait_group 1;" ::: "memory")

#define LDSM4(d, addr) \
    asm volatile("ldmatrix.sync.aligned.m8n8.x4.shared.b16 {%0,%1,%2,%3}, [%4];" \
        : "=r"((d)[0]), "=r"((d)[1]), "=r"((d)[2]), "=r"((d)[3]) : "r"(addr))
#define MMA(c, a, b0, b1) \
    asm volatile("mma.sync.aligned.m16n8k16.row.col.f32.f16.f16.f32 " \
        "{%0,%1,%2,%3}, {%4,%5,%6,%7}, {%8,%9}, {%0,%1,%2,%3};" \
        : "+f"((c)[0]), "+f"((c)[1]), "+f"((c)[2]), "+f"((c)[3]) \
        : "r"((a)[0]), "r"((a)[1]), "r"((a)[2]), "r"((a)[3]), "r"(b0), "r"(b1))

__device__ __forceinline__ float sigf(float x) { return 1.0f / (1.0f + __expf(-x)); }
__device__ __forceinline__ float tanh_fast(float x) {
    float e = __expf(2.0f * x);
    return 1.0f - 2.0f / (e + 1.0f);
}
__device__ __forceinline__ void split_f16(float v, __half& hi, __half& lo) {
    hi = __float2half_rn(v);
    lo = __float2half_rn(v - __half2float(hi));
}
__device__ __forceinline__ uint32_t pack2h(__half a, __half b) {
    __half2 t; t.x = a; t.y = b; return *(uint32_t*)&t;
}

// loader (256 threads): row lr=tid>>1, half cp0=(tid&1)*4; 2 subtiles x 4 cp16
#define LOAD_STAGE(stoff, k0) do {                                                 \
    _Pragma("unroll")                                                              \
    for (int i = 0; i < 4; ++i) {                                                  \
        int c = cp0 + i;                                                           \
        uint32_t so = (uint32_t)(lr * 128 + ((c ^ (lr & 7)) << 4));                \
        cp16(sb + (stoff) + ST_A + so, pA + (k0) + c * 8);                         \
        cp16(sb + (stoff) + ST_B + so, pB + (k0) + c * 8);                         \
    }                                                                              \
    CP_COMMIT();                                                                   \
} while (0)

// ---------------- prep kernels ----------------
__global__ void prep_fold(const float* __restrict__ W_ih, const float* __restrict__ W_hh,
                          const float* __restrict__ b_ih, const float* __restrict__ b_hh) {
    int idx = blockIdx.x * 256 + threadIdx.x;
    if (idx >= 4 * HID * HID) return;
    int k = idx & (HID - 1);
    int j = (idx >> 10) & (HID - 1);
    int g = idx >> 20;

    float w, ws1;
    if (g == 0) {
        float a = W_ih[j * HID + k], b = W_hh[j * HID + k];
        w = a + b; ws1 = b;
    } else if (g == 1) {
        int r = HID + j;
        float a = W_ih[r * HID + k], b = W_hh[r * HID + k];
        w = a + b; ws1 = b;
    } else if (g == 2) {
        int r = 2 * HID + j;
        w = W_ih[r * HID + k]; ws1 = 0.0f;
    } else {
        int r = 2 * HID + j;
        w = W_hh[r * HID + k]; ws1 = w;
    }
    g_Wf[0][idx] = __float2half_rn(w);
    g_Wf[1][idx] = __float2half_rn(ws1);

    if (k == 0) {
        float bb;
        if (g == 0)      bb = b_ih[j] + b_hh[j];
        else if (g == 1) bb = b_ih[HID + j] + b_hh[HID + j];
        else if (g == 2) bb = b_ih[2 * HID + j];
        else             bb = b_hh[2 * HID + j];
        g_b4[g * HID + j] = bb;
    }
}

__global__ void prep_wout(const float* __restrict__ W_out) {
    int idx = blockIdx.x * 256 + threadIdx.x;
    if (idx >= HID * HID) return;
    g_WOf[idx] = __float2half_rn(W_out[idx]);
}

__global__ void prep_h(const float* __restrict__ hidden) {
    int idx = blockIdx.x * 256 + threadIdx.x;
    if (idx >= BATCH * HID) return;
    __half hi, lo;
    split_f16(hidden[idx], hi, lo);
    g_hhi[0][idx] = hi; g_hlo[0][idx] = lo;
}

// ---------------- gate GEMM + GRU pointwise ----------------
// grid (32, 32): bx = 32-j tile, by = 128-row batch tile. CTA N = 4 gates x 32 j.
// 8 warps, 2x4 grid, warp tile 64x32. Single fp16 pass; B via paired LDSM4.
__global__ __launch_bounds__(256, 2)
void gate_mma(int wsel, int src, int dst) {
    extern __shared__ char smem[];
    uint32_t sb = smem_u32(smem);
    int tid = threadIdx.x;
    int lane = tid & 31, wid = tid >> 5;
    int wm = wid >> 2, wn = wid & 3;
    int rowbase = blockIdx.y * 128;
    int jbase   = blockIdx.x * 32;

    // loader mapping
    int lr = tid >> 1;
    int cp0 = (tid & 1) * 4;
    const __half* pA = g_hhi[src] + (size_t)(rowbase + lr) * HID;
    const __half* pB = g_Wf[wsel] + (size_t)((lr >> 5) * HID + jbase + (lr & 31)) * HID;

    float acc[4][4][4];
#pragma unroll
    for (int a = 0; a < 4; ++a)
#pragma unroll
        for (int b = 0; b < 4; ++b)
#pragma unroll
            for (int c = 0; c < 4; ++c) acc[a][b][c] = 0.0f;

    LOAD_STAGE(0, 0);
    LOAD_STAGE(ST_SZ, BK);

    int a_row0 = wm * 64 + (lane & 15);
    int a_chi = lane >> 4;
    // B paired-LDSM4 mapping: group g=lane>>3: nfo=g>>1, chunk=g&1
    int b_nfo = (lane >> 4) * 8;
    int b_chk = (lane >> 3) & 1;
    int b_lrow = lane & 7;

    for (int cc = 0; cc < NCH; ++cc) {
        uint32_t st = sb + (uint32_t)((cc % 3) * ST_SZ);
        CP_WAIT1();
        __syncthreads();
        if (cc + 2 < NCH) {
            uint32_t st2 = (uint32_t)(((cc + 2) % 3) * ST_SZ);
            int k0 = (cc + 2) * BK;
            LOAD_STAGE(st2, k0);
        } else {
            CP_COMMIT();
        }

#pragma unroll
        for (int kk = 0; kk < 4; ++kk) {
            uint32_t Ah[4][4];
#pragma unroll
            for (int mf = 0; mf < 4; ++mf) {
                int row = a_row0 + mf * 16;
                uint32_t so = (uint32_t)(row * 128 + (((2 * kk + a_chi) ^ (row & 7)) << 4));
                LDSM4(Ah[mf], st + ST_A + so);
            }
            uint32_t bh[4][2];
#pragma unroll
            for (int np = 0; np < 2; ++np) {
                int row = wn * 32 + np * 16 + b_nfo + b_lrow;
                uint32_t so = (uint32_t)(row * 128 + (((2 * kk + b_chk) ^ (row & 7)) << 4));
                uint32_t t[4];
                LDSM4(t, st + ST_B + so);
                bh[np * 2][0] = t[0]; bh[np * 2][1] = t[1];
                bh[np * 2 + 1][0] = t[2]; bh[np * 2 + 1][1] = t[3];
            }
#pragma unroll
            for (int nf = 0; nf < 4; ++nf)
#pragma unroll
                for (int mf = 0; mf < 4; ++mf)
                    MMA(acc[mf][nf], Ah[mf], bh[nf][0], bh[nf][1]);
        }
    }
    __syncthreads();

    // ---- exchange accs through smem: Cs[128][132] ----
    float* Cs = (float*)smem;
#pragma unroll
    for (int mf = 0; mf < 4; ++mf)
#pragma unroll
        for (int nf = 0; nf < 4; ++nf) {
            int m = wm * 64 + mf * 16 + (lane >> 2);
            int n = wn * 32 + nf * 8 + (lane & 3) * 2;
            Cs[m * 132 + n]           = acc[mf][nf][0];
            Cs[m * 132 + n + 1]       = acc[mf][nf][1];
            Cs[(m + 8) * 132 + n]     = acc[mf][nf][2];
            Cs[(m + 8) * 132 + n + 1] = acc[mf][nf][3];
        }
    __syncthreads();

    // ---- GRU pointwise: thread -> row m=tid/2, 16 j values ----
    {
        int m = tid >> 1;
        int j0l = (tid & 1) * 16;
        int j0 = jbase + j0l;
        size_t hoff = (size_t)(rowbase + m) * HID + j0;

        __half hhb[16], hlb[16];
        *(uint4*)&hhb[0] = *(const uint4*)(g_hhi[src] + hoff);
        *(uint4*)&hhb[8] = *(const uint4*)(g_hhi[src] + hoff + 8);
        *(uint4*)&hlb[0] = *(const uint4*)(g_hlo[src] + hoff);
        *(uint4*)&hlb[8] = *(const uint4*)(g_hlo[src] + hoff + 8);

        uint32_t ohh[8], ohl[8], orh[8];
#pragma unroll
        for (int p = 0; p < 8; ++p) {
            __half ehh[2], ehl[2], erh[2];
#pragma unroll
            for (int u = 0; u < 2; ++u) {
                int i = 2 * p + u;
                int jl = j0l + i;
                int j = j0 + i;
                float vr = Cs[m * 132 + jl]      + g_b4[j];
                float vz = Cs[m * 132 + 32 + jl] + g_b4[HID + j];
                float vi = Cs[m * 132 + 64 + jl] + g_b4[2 * HID + j];
                float vh = Cs[m * 132 + 96 + jl] + g_b4[3 * HID + j];
                float rg = sigf(vr);
                float zz = sigf(vz);
                float nn = tanh_fast(vi + rg * vh);
                float hp = __half2float(hhb[i]) + __half2float(hlb[i]);
                float hn = (1.0f - zz) * nn + zz * hp;
                split_f16(hn, ehh[u], ehl[u]);
                erh[u] = __float2half_rn(fmaxf(hn, 0.0f));
            }
            ohh[p] = pack2h(ehh[0], ehh[1]);
            ohl[p] = pack2h(ehl[0], ehl[1]);
            orh[p] = pack2h(erh[0], erh[1]);
        }
        *(uint4*)(g_hhi[dst] + hoff)     = make_uint4(ohh[0], ohh[1], ohh[2], ohh[3]);
        *(uint4*)(g_hhi[dst] + hoff + 8) = make_uint4(ohh[4], ohh[5], ohh[6], ohh[7]);
        *(uint4*)(g_hlo[dst] + hoff)     = make_uint4(ohl[0], ohl[1], ohl[2], ohl[3]);
        *(uint4*)(g_hlo[dst] + hoff + 8) = make_uint4(ohl[4], ohl[5], ohl[6], ohl[7]);
        *(uint4*)(g_rhi + hoff)          = make_uint4(orh[0], orh[1], orh[2], orh[3]);
        *(uint4*)(g_rhi + hoff + 8)      = make_uint4(orh[4], orh[5], orh[6], orh[7]);
    }
}

// ---------------- output projection ----------------
// grid (8, 32): bx = 128-col tile, by = 128-row batch tile. 8 warps, 2x4, 64x32.
__global__ __launch_bounds__(256, 2)
void out_mma(const float* __restrict__ bout, float* __restrict__ out) {
    extern __shared__ char smem[];
    uint32_t sb = smem_u32(smem);
    int tid = threadIdx.x;
    int lane = tid & 31, wid = tid >> 5;
    int wm = wid >> 2, wn = wid & 3;
    int rowbase = blockIdx.y * 128;
    int colbase = blockIdx.x * 128;

    int lr = tid >> 1;
    int cp0 = (tid & 1) * 4;
    const __half* pA = g_rhi + (size_t)(rowbase + lr) * HID;
    const __half* pB = g_WOf + (size_t)(colbase + lr) * HID;

    float acc[4][4][4];
#pragma unroll
    for (int a = 0; a < 4; ++a)
#pragma unroll
        for (int b = 0; b < 4; ++b)
#pragma unroll
            for (int c = 0; c < 4; ++c) acc[a][b][c] = 0.0f;

    LOAD_STAGE(0, 0);
    LOAD_STAGE(ST_SZ, BK);

    int a_row0 = wm * 64 + (lane & 15);
    int a_chi = lane >> 4;
    int b_nfo = (lane >> 4) * 8;
    int b_chk = (lane >> 3) & 1;
    int b_lrow = lane & 7;

    for (int cc = 0; cc < NCH; ++cc) {
        uint32_t st = sb + (uint32_t)((cc % 3) * ST_SZ);
        CP_WAIT1();
        __syncthreads();
        if (cc + 2 < NCH) {
            uint32_t st2 = (uint32_t)(((cc + 2) % 3) * ST_SZ);
            int k0 = (cc + 2) * BK;
            LOAD_STAGE(st2, k0);
        } else {
            CP_COMMIT();
        }

#pragma unroll
        for (int kk = 0; kk < 4; ++kk) {
            uint32_t Ah[4][4];
#pragma unroll
            for (int mf = 0; mf < 4; ++mf) {
                int row = a_row0 + mf * 16;
                uint32_t so = (uint32_t)(row * 128 + (((2 * kk + a_chi) ^ (row & 7)) << 4));
                LDSM4(Ah[mf], st + ST_A + so);
            }
            uint32_t bh[4][2];
#pragma unroll
            for (int np = 0; np < 2; ++np) {
                int row = wn * 32 + np * 16 + b_nfo + b_lrow;
                uint32_t so = (uint32_t)(row * 128 + (((2 * kk + b_chk) ^ (row & 7)) << 4));
                uint32_t t[4];
                LDSM4(t, st + ST_B + so);
                bh[np * 2][0] = t[0]; bh[np * 2][1] = t[1];
                bh[np * 2 + 1][0] = t[2]; bh[np * 2 + 1][1] = t[3];
            }
#pragma unroll
            for (int nf = 0; nf < 4; ++nf)
#pragma unroll
                for (int mf = 0; mf < 4; ++mf)
                    MMA(acc[mf][nf], Ah[mf], bh[nf][0], bh[nf][1]);
        }
    }

    // ---- bias epilogue, direct from fragments ----
#pragma unroll
    for (int mf = 0; mf < 4; ++mf)
#pragma unroll
        for (int nf = 0; nf < 4; ++nf) {
            int m = rowbase + wm * 64 + mf * 16 + (lane >> 2);
            int n = colbase + wn * 32 + nf * 8 + (lane & 3) * 2;
            float b0 = bout[n], b1 = bout[n + 1];
            float2 v0 = make_float2(acc[mf][nf][0] + b0, acc[mf][nf][1] + b1);
            float2 v1 = make_float2(acc[mf][nf][2] + b0, acc[mf][nf][3] + b1);
            *(float2*)(out + (size_t)m * 1024 + n)       = v0;
            *(float2*)(out + (size_t)(m + 8) * 1024 + n) = v1;
        }
}

// ---------------- launch ----------------
extern "C" void kernel_launch(void* const* d_in, const int* in_sizes, int n_in,
                              void* d_out, int out_size) {
    const float* hidden = (const float*)d_in[0];  // (1, 4096, 1024)
    const float* W_ih   = (const float*)d_in[1];  // (3072, 1024)
    const float* W_hh   = (const float*)d_in[2];  // (3072, 1024)
    const float* b_ih   = (const float*)d_in[3];
    const float* b_hh   = (const float*)d_in[4];
    const float* W_out  = (const float*)d_in[5];  // (1024, 1024)
    const float* b_out  = (const float*)d_in[6];
    float* out = (float*)d_out;                    // (16, 4096, 1024)

    cudaFuncSetAttribute(gate_mma, cudaFuncAttributeMaxDynamicSharedMemorySize, SMEM_TOTAL);
    cudaFuncSetAttribute(out_mma,  cudaFuncAttributeMaxDynamicSharedMemorySize, SMEM_TOTAL);

    prep_fold<<<(4 * HID * HID) / 256, 256>>>(W_ih, W_hh, b_ih, b_hh);
    prep_wout<<<(HID * HID) / 256, 256>>>(W_out);
    prep_h<<<(BATCH * HID) / 256, 256>>>(hidden);

    dim3 ggrid(32, 32);
    dim3 ogrid(8, 32);

    for (int t = 0; t < STEPS; ++t) {
        int wsel = (t == 0) ? 1 : 0;
        int src = t & 1;
        int dst = (t + 1) & 1;
        gate_mma<<<ggrid, 256, SMEM_TOTAL>>>(wsel, src, dst);
        out_mma<<<ogrid, 256, SMEM_TOTAL>>>(b_out, out + (size_t)t * BATCH * 1024);
    }
}